// round 4
// baseline (speedup 1.0000x reference)
#include <cuda_runtime.h>
#include <math.h>

// Problem constants
#define B_    8
#define T_    4096
#define DIM_  1024
#define DIN_  512
#define DBR_  256
#define HBR_  8
#define TP_   4100      // padded length (same for both branches: -4096 % 10 == -4096 % 20 == 4)
#define NW1_  410       // windows, branch 1 (w=10)
#define NW2_  205       // windows, branch 2 (w=20)

// -------- device scratch (static: no allocation allowed) --------
__device__ float g_xi  [B_*T_*DIN_];        // down output -> rmsnorm'd (in place)
__device__ float g_x1p [B_*TP_*DBR_];       // branch1 padded+rolled input
__device__ float g_x2p [B_*TP_*DBR_];
__device__ float g_qkv1[B_*TP_*3*DBR_];
__device__ float g_qkv2[B_*TP_*3*DBR_];
__device__ float g_ao1 [B_*TP_*DBR_];       // attention output (rolled space)
__device__ float g_ao2 [B_*TP_*DBR_];
__device__ float g_po1 [B_*TP_*DBR_];       // proj output (rolled space)
__device__ float g_po2 [B_*TP_*DBR_];
__device__ float g_xcat[B_*T_*DIN_];        // concat(o1,o2) after unroll
__device__ float g_xmid[B_*T_*DIM_];        // residual + up
__device__ float g_h   [B_*T_*DIM_];        // rmsnorm2
__device__ float g_ffn [B_*T_*2*DIM_];      // gelu(ffn1)

// -------------------- generic tiled SGEMM --------------------
// C[M,N] = A[M,K] @ W[K,N] + bias[N]  (+ epilogue)
// mode 0: plain    mode 1: exact GELU    mode 2: += res[M,N]
// Requires: K % 16 == 0, N % 128 == 0. M guarded.
#define BM 128
#define BN 128
#define BK 16

__global__ __launch_bounds__(256, 2)
void sgemm_kernel(const float* __restrict__ A, const float* __restrict__ W,
                  const float* __restrict__ bias, const float* __restrict__ res,
                  float* __restrict__ C, int M, int N, int K, int mode)
{
    __shared__ float As[BK][BM];   // transposed A tile
    __shared__ float Bs[BK][BN];

    const int tid = threadIdx.x;
    const int tx  = tid & 15;
    const int ty  = tid >> 4;
    const int rowBase = blockIdx.y * BM;
    const int colBase = blockIdx.x * BN;

    float acc[8][8];
    #pragma unroll
    for (int i = 0; i < 8; i++)
        #pragma unroll
        for (int j = 0; j < 8; j++) acc[i][j] = 0.f;

    const int aRow0 = tid >> 2;         // 0..63  (two halves: +64)
    const int aCol0 = (tid & 3) << 2;   // 0,4,8,12
    const int bRow0 = tid >> 5;         // 0..7   (two halves: +8)
    const int bCol0 = (tid & 31) << 2;  // 0..124

    for (int k0 = 0; k0 < K; k0 += BK) {
        #pragma unroll
        for (int h = 0; h < 2; h++) {
            int r  = aRow0 + h * 64;
            int gr = rowBase + r;
            float4 av = make_float4(0.f, 0.f, 0.f, 0.f);
            if (gr < M) av = *(const float4*)(A + (size_t)gr * K + k0 + aCol0);
            As[aCol0 + 0][r] = av.x;
            As[aCol0 + 1][r] = av.y;
            As[aCol0 + 2][r] = av.z;
            As[aCol0 + 3][r] = av.w;
        }
        #pragma unroll
        for (int h = 0; h < 2; h++) {
            int r = bRow0 + h * 8;
            float4 bv = *(const float4*)(W + (size_t)(k0 + r) * N + colBase + bCol0);
            *(float4*)(&Bs[r][bCol0]) = bv;
        }
        __syncthreads();

        #pragma unroll
        for (int kk = 0; kk < BK; kk++) {
            float a[8], b[8];
            *(float4*)&a[0] = *(const float4*)&As[kk][ty * 8];
            *(float4*)&a[4] = *(const float4*)&As[kk][ty * 8 + 4];
            *(float4*)&b[0] = *(const float4*)&Bs[kk][tx * 8];
            *(float4*)&b[4] = *(const float4*)&Bs[kk][tx * 8 + 4];
            #pragma unroll
            for (int i = 0; i < 8; i++)
                #pragma unroll
                for (int j = 0; j < 8; j++)
                    acc[i][j] = fmaf(a[i], b[j], acc[i][j]);
        }
        __syncthreads();
    }

    #pragma unroll
    for (int i = 0; i < 8; i++) {
        int r = rowBase + ty * 8 + i;
        if (r >= M) continue;
        #pragma unroll
        for (int j = 0; j < 8; j++) {
            int c = colBase + tx * 8 + j;
            float v = acc[i][j] + bias[c];
            if (mode == 1) {
                v = 0.5f * v * (1.0f + erff(v * 0.70710678118654752f));
            } else if (mode == 2) {
                v += res[(size_t)r * N + c];
            }
            C[(size_t)r * N + c] = v;
        }
    }
}

// -------------------- RMSNorm (block per row) --------------------
__global__ void rmsnorm_kernel(const float* __restrict__ in, const float* __restrict__ w,
                               float* __restrict__ out, int C)
{
    const int row = blockIdx.x;
    const float* p = in + (size_t)row * C;
    float s = 0.f;
    for (int c = threadIdx.x; c < C; c += blockDim.x) { float v = p[c]; s += v * v; }
    #pragma unroll
    for (int o = 16; o > 0; o >>= 1) s += __shfl_xor_sync(0xffffffffu, s, o);
    __shared__ float red[8];
    __shared__ float scale;
    int wid = threadIdx.x >> 5, lane = threadIdx.x & 31;
    if (lane == 0) red[wid] = s;
    __syncthreads();
    if (threadIdx.x == 0) {
        float t = 0.f;
        for (int i = 0; i < (int)(blockDim.x >> 5); i++) t += red[i];
        scale = rsqrtf(t / (float)C + 1e-6f);
    }
    __syncthreads();
    float sc = scale;
    for (int c = threadIdx.x; c < C; c += blockDim.x)
        out[(size_t)row * C + c] = p[c] * sc * w[c];
}

// -------------------- pad + roll(-shift) + split --------------------
// xp[b, t, c] = (t' = (t+shift) mod Tp) < T ? xi[b, t', off+c] : 0
__global__ void pack_kernel(const float* __restrict__ xi, float* __restrict__ xp,
                            int off, int shift)
{
    int idx = blockIdx.x * blockDim.x + threadIdx.x;
    const int total = B_ * TP_ * DBR_;
    if (idx >= total) return;
    int c = idx & (DBR_ - 1);
    int t = (idx / DBR_) % TP_;
    int b = idx / (DBR_ * TP_);
    int ts = t + shift; if (ts >= TP_) ts -= TP_;
    float v = 0.f;
    if (ts < T_) v = xi[((size_t)b * T_ + ts) * DIN_ + off + c];
    xp[idx] = v;
}

// -------------------- roll(+shift), truncate, write into concat --------------------
__global__ void unshift_kernel(const float* __restrict__ po, float* __restrict__ xcat,
                               int off, int shift)
{
    int idx = blockIdx.x * blockDim.x + threadIdx.x;
    const int total = B_ * TP_ * DBR_;
    if (idx >= total) return;
    int c = idx & (DBR_ - 1);
    int r = (idx / DBR_) % TP_;
    int b = idx / (DBR_ * TP_);
    int t = r + shift; if (t >= TP_) t -= TP_;
    if (t < T_) xcat[((size_t)b * T_ + t) * DIN_ + off + c] = po[idx];
}

// -------------------- windowed attention: one warp per (b, window, head) --------
// qkv: [B*Tp, 768] (Q | K | V, head h at h*32). ao: [B*Tp, 256].
// Max smem slice: 3*w*32 + w*w = 2320 floats (w=20); 4 warps/block.
#define ATT_SLICE 2336
__global__ __launch_bounds__(128)
void attn_kernel(const float* __restrict__ qkv, float* __restrict__ ao,
                 const float* __restrict__ rpb, int w, int nW, int shift)
{
    __shared__ float sm[4 * ATT_SLICE];
    const int warp = threadIdx.x >> 5, lane = threadIdx.x & 31;
    float* S = sm + warp * ATT_SLICE;
    const int gw = blockIdx.x * 4 + warp;
    const int h = gw & 7;
    const int n = (gw >> 3) % nW;
    const int b = gw / (8 * nW);

    float* q  = S;
    float* k  = S + w * 32;
    float* v  = S + 2 * w * 32;
    float* lg = S + 3 * w * 32;

    const size_t rbase = (size_t)b * TP_ + (size_t)n * w;
    for (int i = 0; i < w; i++) {
        size_t ro = (rbase + i) * 768 + h * 32 + lane;
        q[i * 32 + lane] = qkv[ro];
        k[i * 32 + lane] = qkv[ro + 256];
        v[i * 32 + lane] = qkv[ro + 512];
    }
    __syncwarp();

    const float scale = 0.17677669529663687f;   // 32^-0.5
    const bool lastwin = (n == nW - 1);
    for (int p = lane; p < w * w; p += 32) {
        int i = p / w, j = p % w;
        float s = 0.f;
        #pragma unroll
        for (int d = 0; d < 32; d++) s = fmaf(q[i * 32 + d], k[j * 32 + d], s);
        s *= scale;
        s += rpb[(i - j + w - 1) * 8 + h];
        if (lastwin) {
            int mi = (i >= w - shift) ? 2 : 1;
            int mj = (j >= w - shift) ? 2 : 1;
            if (mi != mj) s -= 100.f;
        }
        lg[p] = s;
    }
    __syncwarp();

    if (lane < w) {
        float mx = -3.0e38f;
        for (int j = 0; j < w; j++) mx = fmaxf(mx, lg[lane * w + j]);
        float sum = 0.f;
        for (int j = 0; j < w; j++) { float e = expf(lg[lane * w + j] - mx); lg[lane * w + j] = e; sum += e; }
        float inv = 1.f / sum;
        for (int j = 0; j < w; j++) lg[lane * w + j] *= inv;
    }
    __syncwarp();

    for (int i = 0; i < w; i++) {
        float a = 0.f;
        for (int j = 0; j < w; j++) a = fmaf(lg[i * w + j], v[j * 32 + lane], a);
        ao[(rbase + i) * 256 + h * 32 + lane] = a;
    }
}

// -------------------- launch --------------------
extern "C" void kernel_launch(void* const* d_in, const int* in_sizes, int n_in,
                              void* d_out, int out_size)
{
    (void)in_sizes; (void)n_in; (void)out_size;
    const float* x       = (const float*)d_in[0];
    const float* down_w  = (const float*)d_in[1];
    const float* down_b  = (const float*)d_in[2];
    const float* up_w    = (const float*)d_in[3];
    const float* up_b    = (const float*)d_in[4];
    const float* n1w     = (const float*)d_in[5];
    const float* n2w     = (const float*)d_in[6];
    const float* qkv1_w  = (const float*)d_in[7];
    const float* qkv1_b  = (const float*)d_in[8];
    const float* proj1_w = (const float*)d_in[9];
    const float* proj1_b = (const float*)d_in[10];
    const float* rpb1    = (const float*)d_in[11];
    const float* qkv2_w  = (const float*)d_in[12];
    const float* qkv2_b  = (const float*)d_in[13];
    const float* proj2_w = (const float*)d_in[14];
    const float* proj2_b = (const float*)d_in[15];
    const float* rpb2    = (const float*)d_in[16];
    const float* ffn_w1  = (const float*)d_in[17];
    const float* ffn_b1  = (const float*)d_in[18];
    const float* ffn_w2  = (const float*)d_in[19];
    const float* ffn_b2  = (const float*)d_in[20];
    float* out = (float*)d_out;

    float *xi, *x1p, *x2p, *qk1, *qk2, *ao1, *ao2, *po1, *po2, *xcat, *xmid, *hbuf, *ffn;
    cudaGetSymbolAddress((void**)&xi,   g_xi);
    cudaGetSymbolAddress((void**)&x1p,  g_x1p);
    cudaGetSymbolAddress((void**)&x2p,  g_x2p);
    cudaGetSymbolAddress((void**)&qk1,  g_qkv1);
    cudaGetSymbolAddress((void**)&qk2,  g_qkv2);
    cudaGetSymbolAddress((void**)&ao1,  g_ao1);
    cudaGetSymbolAddress((void**)&ao2,  g_ao2);
    cudaGetSymbolAddress((void**)&po1,  g_po1);
    cudaGetSymbolAddress((void**)&po2,  g_po2);
    cudaGetSymbolAddress((void**)&xcat, g_xcat);
    cudaGetSymbolAddress((void**)&xmid, g_xmid);
    cudaGetSymbolAddress((void**)&hbuf, g_h);
    cudaGetSymbolAddress((void**)&ffn,  g_ffn);

    const int MT = B_ * T_;    // 32768
    const int MP = B_ * TP_;   // 32800
    const int PACK_TOT = B_ * TP_ * DBR_;

    // 1. down-projection + rmsnorm1 (in place)
    sgemm_kernel<<<dim3(DIN_ / BN, (MT + BM - 1) / BM), 256>>>(
        x, down_w, down_b, nullptr, xi, MT, DIN_, DIM_, 0);
    rmsnorm_kernel<<<MT, 256>>>(xi, n1w, xi, DIN_);

    // 2. pad + roll(-shift) + split halves
    pack_kernel<<<(PACK_TOT + 255) / 256, 256>>>(xi, x1p, 0,    5);
    pack_kernel<<<(PACK_TOT + 255) / 256, 256>>>(xi, x2p, DBR_, 10);

    // 3. QKV GEMMs
    sgemm_kernel<<<dim3(768 / BN, (MP + BM - 1) / BM), 256>>>(
        x1p, qkv1_w, qkv1_b, nullptr, qk1, MP, 768, DBR_, 0);
    sgemm_kernel<<<dim3(768 / BN, (MP + BM - 1) / BM), 256>>>(
        x2p, qkv2_w, qkv2_b, nullptr, qk2, MP, 768, DBR_, 0);

    // 4. windowed attention (warp per b,window,head)
    attn_kernel<<<B_ * NW1_ * HBR_ / 4, 128>>>(qk1, ao1, rpb1, 10, NW1_, 5);
    attn_kernel<<<B_ * NW2_ * HBR_ / 4, 128>>>(qk2, ao2, rpb2, 20, NW2_, 10);

    // 5. output projections
    sgemm_kernel<<<dim3(DBR_ / BN, (MP + BM - 1) / BM), 256>>>(
        ao1, proj1_w, proj1_b, nullptr, po1, MP, DBR_, DBR_, 0);
    sgemm_kernel<<<dim3(DBR_ / BN, (MP + BM - 1) / BM), 256>>>(
        ao2, proj2_w, proj2_b, nullptr, po2, MP, DBR_, DBR_, 0);

    // 6. roll(+shift), truncate, concat
    unshift_kernel<<<(PACK_TOT + 255) / 256, 256>>>(po1, xcat, 0,    5);
    unshift_kernel<<<(PACK_TOT + 255) / 256, 256>>>(po2, xcat, DBR_, 10);

    // 7. up-projection + residual
    sgemm_kernel<<<dim3(DIM_ / BN, MT / BM), 256>>>(
        xcat, up_w, up_b, x, xmid, MT, DIM_, DIN_, 2);

    // 8. rmsnorm2
    rmsnorm_kernel<<<MT, 256>>>(xmid, n2w, hbuf, DIM_);

    // 9. FFN1 + exact GELU
    sgemm_kernel<<<dim3(2 * DIM_ / BN, MT / BM), 256>>>(
        hbuf, ffn_w1, ffn_b1, nullptr, ffn, MT, 2 * DIM_, DIM_, 1);

    // 10. FFN2 + residual -> output
    sgemm_kernel<<<dim3(DIM_ / BN, MT / BM), 256>>>(
        ffn, ffn_w2, ffn_b2, xmid, out, MT, DIM_, 2 * DIM_, 2);
}

// round 6
// speedup vs baseline: 2.8296x; 2.8296x over previous
#include <cuda_runtime.h>
#include <math.h>
#include <stdint.h>

// ---------------- problem constants ----------------
#define B_    8
#define T_    4096
#define DIM_  1024
#define DIN_  512
#define DBR_  256
#define HBR_  8
#define TP_   4100      // padded length (-4096 % 10 == -4096 % 20 == 4)
#define NW1_  410
#define NW2_  205

// ---------------- device scratch (static) ----------------
__device__ float g_xi  [B_*T_*DIN_];
__device__ float g_x1p [B_*TP_*DBR_];
__device__ float g_x2p [B_*TP_*DBR_];
__device__ float g_qkv1[B_*TP_*3*DBR_];
__device__ float g_qkv2[B_*TP_*3*DBR_];
__device__ float g_ao1 [B_*TP_*DBR_];
__device__ float g_ao2 [B_*TP_*DBR_];
__device__ float g_po1 [B_*TP_*DBR_];
__device__ float g_po2 [B_*TP_*DBR_];
__device__ float g_xcat[B_*T_*DIN_];
__device__ float g_xmid[B_*T_*DIM_];
__device__ float g_h   [B_*T_*DIM_];
__device__ float g_ffn [B_*T_*2*DIM_];
__device__ float g_wt  [5767168];   // transposed (K-major) weights

// offsets (floats) into g_wt
#define O_DOWN  0u          // [512,1024]
#define O_UP    524288u     // [1024,512]
#define O_QKV1  1048576u    // [768,256]
#define O_QKV2  1245184u
#define O_PROJ1 1441792u    // [256,256]
#define O_PROJ2 1507328u
#define O_FFN1  1572864u    // [2048,1024]
#define O_FFN2  3670016u    // [1024,2048]

// ---------------- small PTX helpers (all base-ISA, no 'a' features) ----------
__device__ __forceinline__ uint32_t smem_u32(const void* p) {
    uint32_t a;
    asm("{ .reg .u64 t; cvta.to.shared.u64 t, %1; cvt.u32.u64 %0, t; }" : "=r"(a) : "l"(p));
    return a;
}
__device__ __forceinline__ uint32_t f2tf32(float f) {
    uint32_t r; asm("cvt.rna.tf32.f32 %0, %1;" : "=r"(r) : "f"(f)); return r;
}
__device__ __forceinline__ void mma_tf32(float* d, const uint32_t* a, const uint32_t* b) {
    asm volatile(
        "mma.sync.aligned.m16n8k8.row.col.f32.tf32.tf32.f32 "
        "{%0,%1,%2,%3}, {%4,%5,%6,%7}, {%8,%9}, {%0,%1,%2,%3};"
        : "+f"(d[0]), "+f"(d[1]), "+f"(d[2]), "+f"(d[3])
        : "r"(a[0]), "r"(a[1]), "r"(a[2]), "r"(a[3]), "r"(b[0]), "r"(b[1]));
}
__device__ __forceinline__ void cp_async16(uint32_t dst, const void* src, int szBytes) {
    asm volatile("cp.async.cg.shared.global [%0], [%1], 16, %2;"
                 :: "r"(dst), "l"(src), "r"(szBytes));
}
__device__ __forceinline__ void cp_async16f(uint32_t dst, const void* src) {
    asm volatile("cp.async.cg.shared.global [%0], [%1], 16;"
                 :: "r"(dst), "l"(src));
}
__device__ __forceinline__ void cp_commit() {
    asm volatile("cp.async.commit_group;" ::: "memory");
}
__device__ __forceinline__ void cp_wait1() {
    asm volatile("cp.async.wait_group 1;" ::: "memory");
}
__device__ __forceinline__ void cp_wait0() {
    asm volatile("cp.async.wait_group 0;" ::: "memory");
}

// ---------------- warp-mma tf32 GEMM ----------------
// C[M,N] = A[M,K] @ Wt[N,K]^T + bias    (Wt K-major, pre-rounded to tf32)
// mode 0: plain   mode 1: exact GELU    mode 2: += res[M,N]
// CTA tile 128x128, K-chunk 32. N%128==0, K%32==0. M guarded.
#define GBM 128
#define GBN 128
#define GBK 32
#define AST 36                              // 32 + 4 pad (floats)
#define STAGE_F (GBM*AST + GBN*AST)         // floats per stage (9216)
#define GEMM_SMEM (2 * STAGE_F * 4)         // 73728 bytes

__device__ __forceinline__ void stage_loads(
    const float* __restrict__ A, const float* __restrict__ Wt,
    int M, int K, int rowBase, int colBase, int k0,
    uint32_t asBase, uint32_t bsBase, int tid)
{
    #pragma unroll
    for (int i = 0; i < 4; i++) {
        int idx = tid + i * 256;            // 0..1023
        int r = idx >> 3, c = (idx & 7) << 2;
        int gr = rowBase + r;
        int sz = (gr < M) ? 16 : 0;
        if (gr >= M) gr = M - 1;            // keep address valid
        cp_async16(asBase + (uint32_t)(r * AST + c) * 4u,
                   A + (size_t)gr * K + k0 + c, sz);
    }
    #pragma unroll
    for (int i = 0; i < 4; i++) {
        int idx = tid + i * 256;
        int r = idx >> 3, c = (idx & 7) << 2;
        cp_async16f(bsBase + (uint32_t)(r * AST + c) * 4u,
                    Wt + (size_t)(colBase + r) * K + k0 + c);
    }
    cp_commit();
}

__global__ __launch_bounds__(256, 2)
void mma_gemm(const float* __restrict__ A, const float* __restrict__ Wt,
              const float* __restrict__ bias, const float* __restrict__ res,
              float* __restrict__ C, int M, int N, int K, int mode)
{
    extern __shared__ float sm[];
    const uint32_t smBase = smem_u32(sm);

    const int tid  = threadIdx.x;
    const int wid  = tid >> 5;
    const int lane = tid & 31;
    const int g    = lane >> 2;       // group id (0..7)
    const int tg   = lane & 3;        // thread-in-group
    const int warpRow = wid >> 2;     // 0..1  -> 64-row band
    const int warpCol = wid & 3;      // 0..3  -> 32-col band
    const int rowBase = blockIdx.y * GBM;
    const int colBase = blockIdx.x * GBN;

    float acc[4][4][4];
    #pragma unroll
    for (int mt = 0; mt < 4; mt++)
        #pragma unroll
        for (int nt = 0; nt < 4; nt++)
            #pragma unroll
            for (int i = 0; i < 4; i++) acc[mt][nt][i] = 0.f;

    const int nk = K >> 5;
    // stage s: A at sm + s*STAGE_F, B at +GBM*AST
    stage_loads(A, Wt, M, K, rowBase, colBase, 0,
                smBase, smBase + GBM * AST * 4u, tid);

    for (int kc = 0; kc < nk; kc++) {
        const int s = kc & 1;
        if (kc + 1 < nk) {
            const uint32_t nb = smBase + (uint32_t)((s ^ 1) * STAGE_F) * 4u;
            stage_loads(A, Wt, M, K, rowBase, colBase, (kc + 1) << 5,
                        nb, nb + GBM * AST * 4u, tid);
            cp_wait1();
        } else {
            cp_wait0();
        }
        __syncthreads();

        const float* as = sm + s * STAGE_F;
        const float* bs = as + GBM * AST;
        const float* aw = as + (warpRow * 64 + g) * AST + tg;
        const float* bw = bs + (warpCol * 32 + g) * AST + tg;

        #pragma unroll
        for (int ks = 0; ks < 4; ks++) {
            const int k = ks * 8;
            uint32_t afr[4][4], bfr[4][2];
            #pragma unroll
            for (int mt = 0; mt < 4; mt++) {
                const float* ap = aw + mt * 16 * AST + k;
                afr[mt][0] = f2tf32(ap[0]);
                afr[mt][1] = f2tf32(ap[8 * AST]);
                afr[mt][2] = f2tf32(ap[4]);
                afr[mt][3] = f2tf32(ap[8 * AST + 4]);
            }
            #pragma unroll
            for (int nt = 0; nt < 4; nt++) {
                const float* bp = bw + nt * 8 * AST + k;
                bfr[nt][0] = __float_as_uint(bp[0]);   // pre-rounded tf32
                bfr[nt][1] = __float_as_uint(bp[4]);
            }
            #pragma unroll
            for (int mt = 0; mt < 4; mt++)
                #pragma unroll
                for (int nt = 0; nt < 4; nt++)
                    mma_tf32(acc[mt][nt], afr[mt], bfr[nt]);
        }
        __syncthreads();
    }

    // ---------------- epilogue ----------------
    #pragma unroll
    for (int mt = 0; mt < 4; mt++) {
        #pragma unroll
        for (int nt = 0; nt < 4; nt++) {
            const int r0 = rowBase + warpRow * 64 + mt * 16 + g;
            const int cc = colBase + warpCol * 32 + nt * 8 + 2 * tg;
            const float bx = bias[cc], by = bias[cc + 1];
            #pragma unroll
            for (int h = 0; h < 2; h++) {
                const int row = r0 + h * 8;
                if (row >= M) continue;
                float v0 = acc[mt][nt][2 * h + 0] + bx;
                float v1 = acc[mt][nt][2 * h + 1] + by;
                if (mode == 1) {
                    v0 = 0.5f * v0 * (1.0f + erff(v0 * 0.70710678118654752f));
                    v1 = 0.5f * v1 * (1.0f + erff(v1 * 0.70710678118654752f));
                } else if (mode == 2) {
                    const float2 rv = *(const float2*)(res + (size_t)row * N + cc);
                    v0 += rv.x; v1 += rv.y;
                }
                *(float2*)(C + (size_t)row * N + cc) = make_float2(v0, v1);
            }
        }
    }
}

// ---------------- weight transpose: src[K,N] -> dst[N,K], rounded to tf32 ----
__global__ void transpose_kernel(const float* __restrict__ src, float* __restrict__ dst,
                                 int K, int N)
{
    __shared__ float t[32][33];
    const int kb = blockIdx.y * 32, nb = blockIdx.x * 32;
    const int x = threadIdx.x, y = threadIdx.y;
    #pragma unroll
    for (int i = 0; i < 32; i += 8)
        t[y + i][x] = src[(size_t)(kb + y + i) * N + nb + x];
    __syncthreads();
    #pragma unroll
    for (int i = 0; i < 32; i += 8)
        dst[(size_t)(nb + y + i) * K + kb + x] = __uint_as_float(f2tf32(t[x][y + i]));
}

// ---------------- RMSNorm ----------------
__global__ void rmsnorm_kernel(const float* __restrict__ in, const float* __restrict__ w,
                               float* __restrict__ out, int C)
{
    const int row = blockIdx.x;
    const float* p = in + (size_t)row * C;
    float s = 0.f;
    for (int c = threadIdx.x; c < C; c += blockDim.x) { float v = p[c]; s += v * v; }
    #pragma unroll
    for (int o = 16; o > 0; o >>= 1) s += __shfl_xor_sync(0xffffffffu, s, o);
    __shared__ float red[8];
    __shared__ float scale;
    int wid = threadIdx.x >> 5, lane = threadIdx.x & 31;
    if (lane == 0) red[wid] = s;
    __syncthreads();
    if (threadIdx.x == 0) {
        float t = 0.f;
        for (int i = 0; i < (int)(blockDim.x >> 5); i++) t += red[i];
        scale = rsqrtf(t / (float)C + 1e-6f);
    }
    __syncthreads();
    float sc = scale;
    for (int c = threadIdx.x; c < C; c += blockDim.x)
        out[(size_t)row * C + c] = p[c] * sc * w[c];
}

// ---------------- pad + roll(-shift) + split ----------------
__global__ void pack_kernel(const float* __restrict__ xi, float* __restrict__ xp,
                            int off, int shift)
{
    int idx = blockIdx.x * blockDim.x + threadIdx.x;
    const int total = B_ * TP_ * DBR_;
    if (idx >= total) return;
    int c = idx & (DBR_ - 1);
    int t = (idx / DBR_) % TP_;
    int b = idx / (DBR_ * TP_);
    int ts = t + shift; if (ts >= TP_) ts -= TP_;
    float v = 0.f;
    if (ts < T_) v = xi[((size_t)b * T_ + ts) * DIN_ + off + c];
    xp[idx] = v;
}

// ---------------- roll(+shift), truncate, concat ----------------
__global__ void unshift_kernel(const float* __restrict__ po, float* __restrict__ xcat,
                               int off, int shift)
{
    int idx = blockIdx.x * blockDim.x + threadIdx.x;
    const int total = B_ * TP_ * DBR_;
    if (idx >= total) return;
    int c = idx & (DBR_ - 1);
    int r = (idx / DBR_) % TP_;
    int b = idx / (DBR_ * TP_);
    int t = r + shift; if (t >= TP_) t -= TP_;
    if (t < T_) xcat[((size_t)b * T_ + t) * DIN_ + off + c] = po[idx];
}

// ---------------- windowed attention (warp per b,window,head) ----------------
#define ATT_SLICE 2336
__global__ __launch_bounds__(128)
void attn_kernel(const float* __restrict__ qkv, float* __restrict__ ao,
                 const float* __restrict__ rpb, int w, int nW, int shift)
{
    __shared__ float sm[4 * ATT_SLICE];
    const int warp = threadIdx.x >> 5, lane = threadIdx.x & 31;
    float* S = sm + warp * ATT_SLICE;
    const int gw = blockIdx.x * 4 + warp;
    const int h = gw & 7;
    const int n = (gw >> 3) % nW;
    const int b = gw / (8 * nW);

    float* q  = S;
    float* k  = S + w * 32;
    float* v  = S + 2 * w * 32;
    float* lg = S + 3 * w * 32;

    const size_t rbase = (size_t)b * TP_ + (size_t)n * w;
    for (int i = 0; i < w; i++) {
        size_t ro = (rbase + i) * 768 + h * 32 + lane;
        q[i * 32 + lane] = qkv[ro];
        k[i * 32 + lane] = qkv[ro + 256];
        v[i * 32 + lane] = qkv[ro + 512];
    }
    __syncwarp();

    const float scale = 0.17677669529663687f;
    const bool lastwin = (n == nW - 1);
    for (int p = lane; p < w * w; p += 32) {
        int i = p / w, j = p % w;
        float s = 0.f;
        #pragma unroll
        for (int d = 0; d < 32; d++) s = fmaf(q[i * 32 + d], k[j * 32 + d], s);
        s *= scale;
        s += rpb[(i - j + w - 1) * 8 + h];
        if (lastwin) {
            int mi = (i >= w - shift) ? 2 : 1;
            int mj = (j >= w - shift) ? 2 : 1;
            if (mi != mj) s -= 100.f;
        }
        lg[p] = s;
    }
    __syncwarp();

    if (lane < w) {
        float mx = -3.0e38f;
        for (int j = 0; j < w; j++) mx = fmaxf(mx, lg[lane * w + j]);
        float sum = 0.f;
        for (int j = 0; j < w; j++) { float e = expf(lg[lane * w + j] - mx); lg[lane * w + j] = e; sum += e; }
        float inv = 1.f / sum;
        for (int j = 0; j < w; j++) lg[lane * w + j] *= inv;
    }
    __syncwarp();

    for (int i = 0; i < w; i++) {
        float a = 0.f;
        for (int j = 0; j < w; j++) a = fmaf(lg[i * w + j], v[j * 32 + lane], a);
        ao[(rbase + i) * 256 + h * 32 + lane] = a;
    }
}

// ---------------- launch ----------------
extern "C" void kernel_launch(void* const* d_in, const int* in_sizes, int n_in,
                              void* d_out, int out_size)
{
    (void)in_sizes; (void)n_in; (void)out_size;
    const float* x       = (const float*)d_in[0];
    const float* down_w  = (const float*)d_in[1];
    const float* down_b  = (const float*)d_in[2];
    const float* up_w    = (const float*)d_in[3];
    const float* up_b    = (const float*)d_in[4];
    const float* n1w     = (const float*)d_in[5];
    const float* n2w     = (const float*)d_in[6];
    const float* qkv1_w  = (const float*)d_in[7];
    const float* qkv1_b  = (const float*)d_in[8];
    const float* proj1_w = (const float*)d_in[9];
    const float* proj1_b = (const float*)d_in[10];
    const float* rpb1    = (const float*)d_in[11];
    const float* qkv2_w  = (const float*)d_in[12];
    const float* qkv2_b  = (const float*)d_in[13];
    const float* proj2_w = (const float*)d_in[14];
    const float* proj2_b = (const float*)d_in[15];
    const float* rpb2    = (const float*)d_in[16];
    const float* ffn_w1  = (const float*)d_in[17];
    const float* ffn_b1  = (const float*)d_in[18];
    const float* ffn_w2  = (const float*)d_in[19];
    const float* ffn_b2  = (const float*)d_in[20];
    float* out = (float*)d_out;

    float *xi, *x1p, *x2p, *qk1, *qk2, *ao1, *ao2, *po1, *po2, *xcat, *xmid, *hbuf, *ffn, *wt;
    cudaGetSymbolAddress((void**)&xi,   g_xi);
    cudaGetSymbolAddress((void**)&x1p,  g_x1p);
    cudaGetSymbolAddress((void**)&x2p,  g_x2p);
    cudaGetSymbolAddress((void**)&qk1,  g_qkv1);
    cudaGetSymbolAddress((void**)&qk2,  g_qkv2);
    cudaGetSymbolAddress((void**)&ao1,  g_ao1);
    cudaGetSymbolAddress((void**)&ao2,  g_ao2);
    cudaGetSymbolAddress((void**)&po1,  g_po1);
    cudaGetSymbolAddress((void**)&po2,  g_po2);
    cudaGetSymbolAddress((void**)&xcat, g_xcat);
    cudaGetSymbolAddress((void**)&xmid, g_xmid);
    cudaGetSymbolAddress((void**)&hbuf, g_h);
    cudaGetSymbolAddress((void**)&ffn,  g_ffn);
    cudaGetSymbolAddress((void**)&wt,   g_wt);

    cudaFuncSetAttribute(mma_gemm, cudaFuncAttributeMaxDynamicSharedMemorySize, GEMM_SMEM);

    const int MT = B_ * T_;    // 32768
    const int MP = B_ * TP_;   // 32800
    const int PACK_TOT = B_ * TP_ * DBR_;
    const int MT_TILES = MT / GBM;            // 256
    const int MP_TILES = (MP + GBM - 1) / GBM; // 257

    // 0. transpose all weights to K-major (tf32-rounded)
    transpose_kernel<<<dim3(DIN_/32,  DIM_/32),   dim3(32,8)>>>(down_w,  wt + O_DOWN,  DIM_,  DIN_);
    transpose_kernel<<<dim3(DIM_/32,  DIN_/32),   dim3(32,8)>>>(up_w,    wt + O_UP,    DIN_,  DIM_);
    transpose_kernel<<<dim3(768/32,   DBR_/32),   dim3(32,8)>>>(qkv1_w,  wt + O_QKV1,  DBR_,  768);
    transpose_kernel<<<dim3(768/32,   DBR_/32),   dim3(32,8)>>>(qkv2_w,  wt + O_QKV2,  DBR_,  768);
    transpose_kernel<<<dim3(DBR_/32,  DBR_/32),   dim3(32,8)>>>(proj1_w, wt + O_PROJ1, DBR_,  DBR_);
    transpose_kernel<<<dim3(DBR_/32,  DBR_/32),   dim3(32,8)>>>(proj2_w, wt + O_PROJ2, DBR_,  DBR_);
    transpose_kernel<<<dim3(2*DIM_/32, DIM_/32),  dim3(32,8)>>>(ffn_w1,  wt + O_FFN1,  DIM_,  2*DIM_);
    transpose_kernel<<<dim3(DIM_/32,  2*DIM_/32), dim3(32,8)>>>(ffn_w2,  wt + O_FFN2,  2*DIM_, DIM_);

    // 1. down + rmsnorm1
    mma_gemm<<<dim3(DIN_/GBN, MT_TILES), 256, GEMM_SMEM>>>(
        x, wt + O_DOWN, down_b, nullptr, xi, MT, DIN_, DIM_, 0);
    rmsnorm_kernel<<<MT, 256>>>(xi, n1w, xi, DIN_);

    // 2. pack
    pack_kernel<<<(PACK_TOT + 255) / 256, 256>>>(xi, x1p, 0,    5);
    pack_kernel<<<(PACK_TOT + 255) / 256, 256>>>(xi, x2p, DBR_, 10);

    // 3. QKV
    mma_gemm<<<dim3(768/GBN, MP_TILES), 256, GEMM_SMEM>>>(
        x1p, wt + O_QKV1, qkv1_b, nullptr, qk1, MP, 768, DBR_, 0);
    mma_gemm<<<dim3(768/GBN, MP_TILES), 256, GEMM_SMEM>>>(
        x2p, wt + O_QKV2, qkv2_b, nullptr, qk2, MP, 768, DBR_, 0);

    // 4. attention
    attn_kernel<<<B_ * NW1_ * HBR_ / 4, 128>>>(qk1, ao1, rpb1, 10, NW1_, 5);
    attn_kernel<<<B_ * NW2_ * HBR_ / 4, 128>>>(qk2, ao2, rpb2, 20, NW2_, 10);

    // 5. proj
    mma_gemm<<<dim3(DBR_/GBN, MP_TILES), 256, GEMM_SMEM>>>(
        ao1, wt + O_PROJ1, proj1_b, nullptr, po1, MP, DBR_, DBR_, 0);
    mma_gemm<<<dim3(DBR_/GBN, MP_TILES), 256, GEMM_SMEM>>>(
        ao2, wt + O_PROJ2, proj2_b, nullptr, po2, MP, DBR_, DBR_, 0);

    // 6. unshift + concat
    unshift_kernel<<<(PACK_TOT + 255) / 256, 256>>>(po1, xcat, 0,    5);
    unshift_kernel<<<(PACK_TOT + 255) / 256, 256>>>(po2, xcat, DBR_, 10);

    // 7. up + residual
    mma_gemm<<<dim3(DIM_/GBN, MT_TILES), 256, GEMM_SMEM>>>(
        xcat, wt + O_UP, up_b, x, xmid, MT, DIM_, DIN_, 2);

    // 8. rmsnorm2
    rmsnorm_kernel<<<MT, 256>>>(xmid, n2w, hbuf, DIM_);

    // 9. FFN1 + GELU
    mma_gemm<<<dim3(2*DIM_/GBN, MT_TILES), 256, GEMM_SMEM>>>(
        hbuf, wt + O_FFN1, ffn_b1, nullptr, ffn, MT, 2*DIM_, DIM_, 1);

    // 10. FFN2 + residual -> out
    mma_gemm<<<dim3(DIM_/GBN, MT_TILES), 256, GEMM_SMEM>>>(
        ffn, wt + O_FFN2, ffn_b2, xmid, out, MT, DIM_, 2*DIM_, 2);
}